// round 9
// baseline (speedup 1.0000x reference)
#include <cuda_runtime.h>
#include <cstdint>

// ---------------------------------------------------------------------------
// TransitionDown: KNN-group -> shared Linear -> BN -> ReLU -> max over K.
// y = x@W^T once per input point (8x fewer FLOPs); BN stats via multiplicity
// counts fused into the GEMM epilogue; bias cancels; max commutes with the
// monotone BN affine (min used when scale<0).
// KNN: exact threshold-filtered two-pass, 4-way candidate split; pass B is
// branchless via local-memory overwrite (no BSSY/BSYNC envelopes, no asm).
// Single stream, graph-capture-safe (no stream/event objects).
// ---------------------------------------------------------------------------

#define BATCH 8
#define NPTS  4096
#define SQ    2048
#define KNN   16
#define CIN   128
#define COUT  256
#define NROWS (BATCH * NPTS)   // 32768
#define NQ    (BATCH * SQ)     // 16384
#define BN_EPS 1e-5f
#define NSEG  4
#define SEGN  (NPTS / NSEG)    // 1024 candidates per thread
#define BUFCAP 48

__device__ float g_y[(size_t)NROWS * COUT];   // 33.5 MB
__device__ int   g_idx[(size_t)NQ * KNN];
__device__ int   g_cnt[NROWS];                // zero at module load + by k_pool
__device__ float g_psum[256 * COUT];
__device__ float g_psumsq[256 * COUT];
__device__ float g_scale[COUT];
__device__ float g_shift[COUT];

#define FMA2(d, a, b, c) \
    asm("fma.rn.f32x2 %0, %1, %2, %3;" : "=l"(d) : "l"(a), "l"(b), "l"(c))
#define DUP2(d, a) \
    asm("mov.b64 %0, {%1, %1};" : "=l"(d) : "r"(a))
#define UNPK2(lo, hi, v) \
    asm("mov.b64 {%0, %1}, %2;" : "=f"(lo), "=f"(hi) : "l"(v))

// Distance bitwise-replicating the reference fp32 pattern:
//   dot = fma(q2,p2, fma(q1,p1, mul(q0,p0)))
//   d   = add(fma(-2, dot, |q|^2), |p|^2)
#define DIST(qq, p) \
    __fadd_rn(__fmaf_rn(-2.0f, \
        __fmaf_rn((qq).z, (p).z, __fmaf_rn((qq).y, (p).y, __fmul_rn((qq).x, (p).x))), \
        (qq).w), (p).w)

// ---------------------------------------------------------------------------
// KNN: 256 blocks x 256 threads = 64 queries x 4 segments (1024 cand each).
// ---------------------------------------------------------------------------
__global__ void __launch_bounds__(256) k_knn(const float* __restrict__ xyz,
                                             float* __restrict__ out_xyz,
                                             int write_xyz) {
    extern __shared__ float4 sp[];                 // 4096*16B = 64 KB
    float* md = (float*)(sp + NPTS);               // [64][4][16]  16 KB
    int*   mi = (int*)(md + 64 * NSEG * KNN);      // [64][4][16]  16 KB

    const int b     = blockIdx.x >> 5;             // 32 blocks / batch
    const int sbase = (blockIdx.x & 31) * 64;
    const int tid   = threadIdx.x;
    const int seg   = tid >> 6;                    // 0..3
    const int q     = tid & 63;                    // 0..63

    for (int i = tid; i < NPTS; i += 256) {
        const float* p = xyz + ((size_t)b * NPTS + i) * 3;
        float px = p[0], py = p[1], pz = p[2];
        float pw = __fmaf_rn(pz, pz, __fmaf_rn(py, py, __fmul_rn(px, px)));
        sp[i] = make_float4(px, py, pz, pw);
    }
    __syncthreads();

    const int s = sbase + q;
    const float4 qq = sp[s];
    const int nbeg = seg * SEGN;

    // ---- Pass A: branchless 32 slot-minima (32 candidates per slot) -------
    float v[32];
#pragma unroll
    for (int j = 0; j < 32; ++j) v[j] = 3.4e38f;
    for (int nb = 0; nb < SEGN; nb += 32) {
#pragma unroll
        for (int j = 0; j < 16; ++j) {
            float4 p = sp[nbeg + nb + j];
            v[j] = fminf(v[j], DIST(qq, p));
        }
#pragma unroll
        for (int j = 0; j < 16; ++j) {
            float4 p = sp[nbeg + nb + 16 + j];
            v[16 + j] = fminf(v[16 + j], DIST(qq, p));
        }
    }

    // ---- T = 16th smallest of 32 slot-minima (register bitonic) -----------
    // Provably T >= true 16th-smallest distance in this segment (>=16
    // candidates have d <= T), so the pass-B survivor set contains the
    // exact top-16 including all ties.
#pragma unroll
    for (int k = 2; k <= 32; k <<= 1) {
#pragma unroll
        for (int j = k >> 1; j > 0; j >>= 1) {
#pragma unroll
            for (int i = 0; i < 32; ++i) {
                int l = i ^ j;
                if (l > i) {
                    bool up = ((i & k) == 0);
                    float lo = fminf(v[i], v[l]);
                    float hi = fmaxf(v[i], v[l]);
                    v[i] = up ? lo : hi;
                    v[l] = up ? hi : lo;
                }
            }
        }
    }
    const float T = v[15];

    // ---- Pass B: branchless local-overwrite survivor collection -----------
    // Unconditional store into slot min(cnt,CAP-1); cnt advances only on
    // survivors, so non-survivor writes land in a dead slot and are
    // overwritten. No branches -> no BSSY/BSYNC envelopes; STL wavefronts
    // are lane-coalesced; ptxas pipelines the LDS stream freely.
    int lbuf[BUFCAP];
    int cnt = 0;
#pragma unroll 4
    for (int n = nbeg; n < nbeg + SEGN; ++n) {
        float4 p = sp[n];
        float d = DIST(qq, p);
        lbuf[min(cnt, BUFCAP - 1)] = n;
        cnt += (d <= T) ? 1 : 0;
    }

    // ---- Exact top-16 among survivors (strict-'<' stable insertion) -------
    float best[KNN];
    int   bidx[KNN];
#pragma unroll
    for (int t = 0; t < KNN; ++t) { best[t] = 3.4e38f; bidx[t] = 0; }

    if (cnt <= BUFCAP) {
        for (int i = 0; i < cnt; ++i) {
            int ci0 = lbuf[i];
            float4 p = sp[ci0];
            float cd = DIST(qq, p);
            if (cd < best[KNN - 1]) {
                int ci = ci0;
#pragma unroll
                for (int t = 0; t < KNN; ++t) {
                    if (cd < best[t]) {
                        float td = best[t]; best[t] = cd; cd = td;
                        int   ti = bidx[t]; bidx[t] = ci; ci = ti;
                    }
                }
            }
        }
    } else {
        // overflow fallback (astronomically rare): exact full rescan
        for (int n = nbeg; n < nbeg + SEGN; ++n) {
            float4 p = sp[n];
            float d = DIST(qq, p);
            if (d < best[KNN - 1]) {
                float cd = d; int ci = n;
#pragma unroll
                for (int t = 0; t < KNN; ++t) {
                    if (cd < best[t]) {
                        float td = best[t]; best[t] = cd; cd = td;
                        int   ti = bidx[t]; bidx[t] = ci; ci = ti;
                    }
                }
            }
        }
    }

    float* mdq = md + (q * NSEG + seg) * KNN;
    int*   miq = mi + (q * NSEG + seg) * KNN;
#pragma unroll
    for (int t = 0; t < KNN; ++t) { mdq[t] = best[t]; miq[t] = bidx[t]; }
    __syncthreads();

    // ---- 4-way tie-preserving merge (seg 0 threads; lowest seg on ties) ---
    if (seg == 0) {
        const float* m0 = md + q * NSEG * KNN;
        const int*   i0 = mi + q * NSEG * KNN;
        int p0 = 0, p1 = 0, p2 = 0, p3 = 0;
        const size_t gi = ((size_t)b * SQ + s) * KNN;
#pragma unroll
        for (int t = 0; t < KNN; ++t) {
            float bd = m0[p0]; int bs = 0;
            float dd;
            dd = m0[1 * 16 + p1]; if (dd < bd) { bd = dd; bs = 1; }
            dd = m0[2 * 16 + p2]; if (dd < bd) { bd = dd; bs = 2; }
            dd = m0[3 * 16 + p3]; if (dd < bd) { bd = dd; bs = 3; }
            int id;
            if      (bs == 0) { id = i0[p0];          p0++; }
            else if (bs == 1) { id = i0[1 * 16 + p1]; p1++; }
            else if (bs == 2) { id = i0[2 * 16 + p2]; p2++; }
            else              { id = i0[3 * 16 + p3]; p3++; }
            g_idx[gi + t] = id;
            atomicAdd(&g_cnt[b * NPTS + id], 1);
        }
        if (write_xyz) {
            float* o = out_xyz + ((size_t)b * SQ + s) * 3;
            o[0] = qq.x; o[1] = qq.y; o[2] = qq.z;
        }
    }
}

// ---------------------------------------------------------------------------
// SGEMM + fused weighted-BN-stats: y = x @ W^T (fp32, FFMA2 accumulators).
// ---------------------------------------------------------------------------
__global__ void __launch_bounds__(256) k_gemm(const float* __restrict__ x,
                                              const float* __restrict__ W) {
    extern __shared__ float sm[];
    float* Xs = sm;                    // [128][128]  Xs[c*128+m]
    float* Ws = sm + 128 * 128;        // [128][128]  Ws[c*128+n]

    const int tid   = threadIdx.x;
    const int mbase = blockIdx.x * 128;
    const int nbase = blockIdx.y * 128;

    for (int e = tid; e < 4096; e += 256) {
        int c4 = e >> 7, m = e & 127;
        float4 v = *(const float4*)(x + (size_t)(mbase + m) * CIN + c4 * 4);
        Xs[(c4 * 4 + 0) * 128 + m] = v.x;
        Xs[(c4 * 4 + 1) * 128 + m] = v.y;
        Xs[(c4 * 4 + 2) * 128 + m] = v.z;
        Xs[(c4 * 4 + 3) * 128 + m] = v.w;
    }
    for (int e = tid; e < 4096; e += 256) {
        int c4 = e >> 7, n = e & 127;
        float4 v = *(const float4*)(W + (size_t)(nbase + n) * CIN + c4 * 4);
        Ws[(c4 * 4 + 0) * 128 + n] = v.x;
        Ws[(c4 * 4 + 1) * 128 + n] = v.y;
        Ws[(c4 * 4 + 2) * 128 + n] = v.z;
        Ws[(c4 * 4 + 3) * 128 + n] = v.w;
    }
    __syncthreads();

    const int w    = tid >> 5;
    const int lane = tid & 31;
    const int m0 = (w & 1) * 64 + (lane & 7) * 8;
    const int n0 = (w >> 1) * 32 + (lane >> 3) * 8;
    const int grp = ((w & 1) << 3) | (lane & 7);    // 16 m-groups

    unsigned long long acc2[8][4];
#pragma unroll
    for (int i = 0; i < 8; ++i)
#pragma unroll
        for (int jp = 0; jp < 4; ++jp) acc2[i][jp] = 0ULL;

#pragma unroll 4
    for (int c = 0; c < CIN; ++c) {
        float a8[8];
        *(float4*)(a8)     = *(const float4*)(Xs + c * 128 + m0);
        *(float4*)(a8 + 4) = *(const float4*)(Xs + c * 128 + m0 + 4);
        ulonglong2 b01 = *(const ulonglong2*)(Ws + c * 128 + n0);
        ulonglong2 b23 = *(const ulonglong2*)(Ws + c * 128 + n0 + 4);
        unsigned long long bb0 = b01.x, bb1 = b01.y, bb2 = b23.x, bb3 = b23.y;
#pragma unroll
        for (int i = 0; i < 8; ++i) {
            unsigned long long aa;
            DUP2(aa, __float_as_uint(a8[i]));
            FMA2(acc2[i][0], aa, bb0, acc2[i][0]);
            FMA2(acc2[i][1], aa, bb1, acc2[i][1]);
            FMA2(acc2[i][2], aa, bb2, acc2[i][2]);
            FMA2(acc2[i][3], aa, bb3, acc2[i][3]);
        }
    }

    float acc[8][8];
#pragma unroll
    for (int i = 0; i < 8; ++i)
#pragma unroll
        for (int jp = 0; jp < 4; ++jp)
            UNPK2(acc[i][2 * jp], acc[i][2 * jp + 1], acc2[i][jp]);

#pragma unroll
    for (int i = 0; i < 8; ++i) {
        float* dst = g_y + (size_t)(mbase + m0 + i) * COUT + nbase + n0;
        *(float4*)(dst)     = make_float4(acc[i][0], acc[i][1], acc[i][2], acc[i][3]);
        *(float4*)(dst + 4) = make_float4(acc[i][4], acc[i][5], acc[i][6], acc[i][7]);
    }

    // ---- fused weighted BN stats ------------------------------------------
    float cw[8];
#pragma unroll
    for (int i = 0; i < 8; ++i) cw[i] = (float)g_cnt[mbase + m0 + i];

    float s[8], sq[8];
#pragma unroll
    for (int j = 0; j < 8; ++j) { s[j] = 0.0f; sq[j] = 0.0f; }
#pragma unroll
    for (int i = 0; i < 8; ++i)
#pragma unroll
        for (int j = 0; j < 8; ++j) {
            float vv = acc[i][j];
            s[j]  = fmaf(cw[i], vv, s[j]);
            sq[j] = fmaf(cw[i] * vv, vv, sq[j]);
        }

    __syncthreads();
    float* red  = sm;                      // [(n)*17 + grp]
    float* red2 = sm + 128 * 17;
#pragma unroll
    for (int j = 0; j < 8; ++j) {
        red [(n0 + j) * 17 + grp] = s[j];
        red2[(n0 + j) * 17 + grp] = sq[j];
    }
    __syncthreads();

    {
        int col  = tid & 127;
        const float* src = (tid < 128) ? red : red2;
        float acc1 = 0.0f;
#pragma unroll
        for (int g = 0; g < 16; ++g) acc1 += src[col * 17 + g];
        float* dst = (tid < 128) ? g_psum : g_psumsq;
        dst[blockIdx.x * COUT + nbase + col] = acc1;
    }
}

// ---------------------------------------------------------------------------
// Finalize: MLP-unrolled partial reduction -> BN scale/shift.
// ---------------------------------------------------------------------------
__global__ void k_finalize(const float* __restrict__ gamma,
                           const float* __restrict__ beta) {
    const int o = threadIdx.x;   // 1 block, 256 threads
    float s0 = 0, s1 = 0, s2 = 0, s3 = 0;
    float q0 = 0, q1 = 0, q2 = 0, q3 = 0;
#pragma unroll 8
    for (int r = 0; r < 64; ++r) {
        s0 += g_psum[(4 * r + 0) * COUT + o];
        s1 += g_psum[(4 * r + 1) * COUT + o];
        s2 += g_psum[(4 * r + 2) * COUT + o];
        s3 += g_psum[(4 * r + 3) * COUT + o];
        q0 += g_psumsq[(4 * r + 0) * COUT + o];
        q1 += g_psumsq[(4 * r + 1) * COUT + o];
        q2 += g_psumsq[(4 * r + 2) * COUT + o];
        q3 += g_psumsq[(4 * r + 3) * COUT + o];
    }
    float s  = (s0 + s1) + (s2 + s3);
    float sq = (q0 + q1) + (q2 + q3);
    const float invn = 1.0f / (float)((size_t)NQ * KNN);
    float mean = s * invn;
    float var  = sq * invn - mean * mean;
    float inv  = rsqrtf(var + BN_EPS);
    float sc   = gamma[o] * inv;
    g_scale[o] = sc;
    g_shift[o] = beta[o] - mean * sc;
}

// ---------------------------------------------------------------------------
// Fused gather + max/min over K + BN affine + ReLU; re-zeroes g_cnt for the
// next replay (module-load zero-init covers the first call).
// ---------------------------------------------------------------------------
__global__ void __launch_bounds__(256) k_pool(float* __restrict__ out) {
    __shared__ int sidx[64];
    const int tid = threadIdx.x;
    if (tid < 64) sidx[tid] = g_idx[(size_t)blockIdx.x * 64 + tid];
    __syncthreads();

    const int qi = tid >> 6;               // 0..3
    const int c4 = tid & 63;               // float4 lane over 256 ch
    const int q  = blockIdx.x * 4 + qi;
    const int b  = q >> 11;
    const float4* yb = (const float4*)g_y + (size_t)b * NPTS * 64;

    float4 mx = make_float4(-3.4e38f, -3.4e38f, -3.4e38f, -3.4e38f);
    float4 mn = make_float4( 3.4e38f,  3.4e38f,  3.4e38f,  3.4e38f);
#pragma unroll
    for (int k = 0; k < KNN; ++k) {
        float4 v = yb[(size_t)sidx[qi * 16 + k] * 64 + c4];
        mx.x = fmaxf(mx.x, v.x); mn.x = fminf(mn.x, v.x);
        mx.y = fmaxf(mx.y, v.y); mn.y = fminf(mn.y, v.y);
        mx.z = fmaxf(mx.z, v.z); mn.z = fminf(mn.z, v.z);
        mx.w = fmaxf(mx.w, v.w); mn.w = fminf(mn.w, v.w);
    }
    float4 sc = ((const float4*)g_scale)[c4];
    float4 sh = ((const float4*)g_shift)[c4];
    float4 r;
    r.x = fmaxf(fmaf(sc.x >= 0.f ? mx.x : mn.x, sc.x, sh.x), 0.f);
    r.y = fmaxf(fmaf(sc.y >= 0.f ? mx.y : mn.y, sc.y, sh.y), 0.f);
    r.z = fmaxf(fmaf(sc.z >= 0.f ? mx.z : mn.z, sc.z, sh.z), 0.f);
    r.w = fmaxf(fmaf(sc.w >= 0.f ? mx.w : mn.w, sc.w, sh.w), 0.f);
    ((float4*)out)[(size_t)q * 64 + c4] = r;

    if (tid < 8) g_cnt[blockIdx.x * 8 + tid] = 0;   // 4096 blocks x 8 = 32768
}

// ---------------------------------------------------------------------------
extern "C" void kernel_launch(void* const* d_in, const int* in_sizes, int n_in,
                              void* d_out, int out_size) {
    const float* x     = (const float*)d_in[0];
    const float* xyz   = (const float*)d_in[1];
    const float* W     = (const float*)d_in[2];
    // d_in[3] = bias: cancels analytically
    const float* gamma = (const float*)d_in[4];
    const float* beta  = (const float*)d_in[5];
    float* out = (float*)d_out;

    const int np_elems  = NQ * COUT;
    const int xyz_elems = NQ * 3;
    const int write_xyz = (out_size >= np_elems + xyz_elems) ? 1 : 0;
    float* out_xyz = out + np_elems;

    const int knn_smem  = NPTS * (int)sizeof(float4) + 64 * NSEG * KNN * 8; // 96 KB
    const int gemm_smem = 2 * 128 * 128 * (int)sizeof(float);               // 128 KB
    cudaFuncSetAttribute(k_knn,  cudaFuncAttributeMaxDynamicSharedMemorySize, knn_smem);
    cudaFuncSetAttribute(k_gemm, cudaFuncAttributeMaxDynamicSharedMemorySize, gemm_smem);

    k_knn<<<BATCH * (SQ / 64), 256, knn_smem>>>(xyz, out_xyz, write_xyz);
    dim3 gg(NROWS / 128, COUT / 128);
    k_gemm<<<gg, 256, gemm_smem>>>(x, W);
    k_finalize<<<1, COUT>>>(gamma, beta);
    k_pool<<<NQ / 4, 256>>>(out);
}

// round 11
// speedup vs baseline: 1.6707x; 1.6707x over previous
#include <cuda_runtime.h>
#include <cstdint>

// ---------------------------------------------------------------------------
// TransitionDown: KNN-group -> shared Linear -> BN -> ReLU -> max over K.
// y = x@W^T once per input point; BN stats via multiplicity counts (fused into
// GEMM epilogue); bias cancels; max commutes with monotone BN affine.
// KNN: exact threshold-filtered two-pass (proven 232us config): branchless
// pass A slot-minima -> bitonic T -> branchy rare-store pass B (int indices)
// -> exact ordered insertion -> tie-preserving 4-way merge.
// GEMM: FFMA2, two K-phases with 64KB smem -> 2 blocks/SM.
// ---------------------------------------------------------------------------

#define BATCH 8
#define NPTS  4096
#define SQ    2048
#define KNN   16
#define CIN   128
#define COUT  256
#define NROWS (BATCH * NPTS)   // 32768
#define NQ    (BATCH * SQ)     // 16384
#define BN_EPS 1e-5f
#define NSEG  4
#define SEGN  (NPTS / NSEG)    // 1024 candidates per thread
#define BUFCAP 48

__device__ float g_y[(size_t)NROWS * COUT];          // 33.5 MB
__device__ int   g_idx[(size_t)NQ * KNN];
__device__ int   g_cnt[NROWS];                       // zero at load + by k_pool
__device__ float g_psum[256 * COUT];
__device__ float g_psumsq[256 * COUT];
__device__ float g_scale[COUT];
__device__ float g_shift[COUT];
__device__ int   g_bufi[(size_t)NQ * NSEG * BUFCAP]; // 12.6 MB survivor indices

#define FMA2(d, a, b, c) \
    asm("fma.rn.f32x2 %0, %1, %2, %3;" : "=l"(d) : "l"(a), "l"(b), "l"(c))
#define DUP2(d, a) \
    asm("mov.b64 %0, {%1, %1};" : "=l"(d) : "r"(a))
#define UNPK2(lo, hi, v) \
    asm("mov.b64 {%0, %1}, %2;" : "=f"(lo), "=f"(hi) : "l"(v))

// Distance bitwise-replicating the reference fp32 pattern:
//   dot = fma(q2,p2, fma(q1,p1, mul(q0,p0)));  d = add(fma(-2,dot,|q|^2),|p|^2)
#define DIST(qq, p) \
    __fadd_rn(__fmaf_rn(-2.0f, \
        __fmaf_rn((qq).z, (p).z, __fmaf_rn((qq).y, (p).y, __fmul_rn((qq).x, (p).x))), \
        (qq).w), (p).w)

// ---------------------------------------------------------------------------
// KNN: 256 blocks x 256 threads = 64 queries x 4 segments (1024 cand each).
// ---------------------------------------------------------------------------
__global__ void __launch_bounds__(256) k_knn(const float* __restrict__ xyz,
                                             float* __restrict__ out_xyz,
                                             int write_xyz) {
    extern __shared__ float4 sp[];                 // 4096*16B = 64 KB
    float* md = (float*)(sp + NPTS);               // [64][4][16]  16 KB
    int*   mi = (int*)(md + 64 * NSEG * KNN);      // [64][4][16]  16 KB

    const int b     = blockIdx.x >> 5;             // 32 blocks / batch
    const int sbase = (blockIdx.x & 31) * 64;
    const int tid   = threadIdx.x;
    const int seg   = tid >> 6;                    // 0..3
    const int q     = tid & 63;                    // 0..63

    for (int i = tid; i < NPTS; i += 256) {
        const float* p = xyz + ((size_t)b * NPTS + i) * 3;
        float px = p[0], py = p[1], pz = p[2];
        float pw = __fmaf_rn(pz, pz, __fmaf_rn(py, py, __fmul_rn(px, px)));
        sp[i] = make_float4(px, py, pz, pw);
    }
    __syncthreads();

    const int s = sbase + q;
    const float4 qq = sp[s];
    const int nbeg = seg * SEGN;

    // ---- Pass A: branchless 32 slot-minima --------------------------------
    float v[32];
#pragma unroll
    for (int j = 0; j < 32; ++j) v[j] = 3.4e38f;
    for (int nb = 0; nb < SEGN; nb += 32) {
#pragma unroll
        for (int j = 0; j < 16; ++j) {
            float4 p = sp[nbeg + nb + j];
            v[j] = fminf(v[j], DIST(qq, p));
        }
#pragma unroll
        for (int j = 0; j < 16; ++j) {
            float4 p = sp[nbeg + nb + 16 + j];
            v[16 + j] = fminf(v[16 + j], DIST(qq, p));
        }
    }

    // ---- T = 16th smallest of 32 slot-minima (register bitonic) -----------
    // T >= true 16th-smallest in this segment => survivors contain top-16.
#pragma unroll
    for (int k = 2; k <= 32; k <<= 1) {
#pragma unroll
        for (int j = k >> 1; j > 0; j >>= 1) {
#pragma unroll
            for (int i = 0; i < 32; ++i) {
                int l = i ^ j;
                if (l > i) {
                    bool up = ((i & k) == 0);
                    float lo = fminf(v[i], v[l]);
                    float hi = fmaxf(v[i], v[l]);
                    v[i] = up ? lo : hi;
                    v[l] = up ? hi : lo;
                }
            }
        }
    }
    const float T = v[15];

    // ---- Pass B: rare-store survivor collection (index only) --------------
    int* bb = g_bufi + ((size_t)blockIdx.x * 256 + tid) * BUFCAP;
    int cnt = 0;
    for (int n = nbeg; n < nbeg + SEGN; ++n) {
        float4 p = sp[n];
        float d = DIST(qq, p);
        if (d <= T) {
            if (cnt < BUFCAP) bb[cnt] = n;
            cnt++;
        }
    }

    // ---- Exact top-16 among survivors (strict-'<' stable insertion) -------
    float best[KNN];
    int   bidx[KNN];
#pragma unroll
    for (int t = 0; t < KNN; ++t) { best[t] = 3.4e38f; bidx[t] = 0; }

    if (cnt <= BUFCAP) {
        for (int i = 0; i < cnt; ++i) {
            int ci0 = bb[i];
            float4 p = sp[ci0];
            float cd = DIST(qq, p);           // identical bits to pass-B d
            if (cd < best[KNN - 1]) {
                int ci = ci0;
#pragma unroll
                for (int t = 0; t < KNN; ++t) {
                    if (cd < best[t]) {
                        float td = best[t]; best[t] = cd; cd = td;
                        int   ti = bidx[t]; bidx[t] = ci; ci = ti;
                    }
                }
            }
        }
    } else {
        // overflow fallback (astronomically rare): exact full rescan
        for (int n = nbeg; n < nbeg + SEGN; ++n) {
            float4 p = sp[n];
            float d = DIST(qq, p);
            if (d < best[KNN - 1]) {
                float cd = d; int ci = n;
#pragma unroll
                for (int t = 0; t < KNN; ++t) {
                    if (cd < best[t]) {
                        float td = best[t]; best[t] = cd; cd = td;
                        int   ti = bidx[t]; bidx[t] = ci; ci = ti;
                    }
                }
            }
        }
    }

    float* mdq = md + (q * NSEG + seg) * KNN;
    int*   miq = mi + (q * NSEG + seg) * KNN;
#pragma unroll
    for (int t = 0; t < KNN; ++t) { mdq[t] = best[t]; miq[t] = bidx[t]; }
    __syncthreads();

    // ---- 4-way tie-preserving merge (seg 0 threads; lowest seg on ties) ---
    if (seg == 0) {
        const float* m0 = md + q * NSEG * KNN;
        const int*   i0 = mi + q * NSEG * KNN;
        int p0 = 0, p1 = 0, p2 = 0, p3 = 0;
        const size_t gi = ((size_t)b * SQ + s) * KNN;
#pragma unroll
        for (int t = 0; t < KNN; ++t) {
            float bd = m0[p0]; int bs = 0;
            float dd;
            dd = m0[1 * 16 + p1]; if (dd < bd) { bd = dd; bs = 1; }
            dd = m0[2 * 16 + p2]; if (dd < bd) { bd = dd; bs = 2; }
            dd = m0[3 * 16 + p3]; if (dd < bd) { bd = dd; bs = 3; }
            int id;
            if      (bs == 0) { id = i0[p0];          p0++; }
            else if (bs == 1) { id = i0[1 * 16 + p1]; p1++; }
            else if (bs == 2) { id = i0[2 * 16 + p2]; p2++; }
            else              { id = i0[3 * 16 + p3]; p3++; }
            g_idx[gi + t] = id;
            atomicAdd(&g_cnt[b * NPTS + id], 1);
        }
        if (write_xyz) {
            float* o = out_xyz + ((size_t)b * SQ + s) * 3;
            o[0] = qq.x; o[1] = qq.y; o[2] = qq.z;
        }
    }
}

// ---------------------------------------------------------------------------
// SGEMM + fused weighted-BN-stats: y = x @ W^T (fp32, FFMA2 accumulators).
// Two K-phases (c 0..63 then 64..127, same FMA order -> bitwise-identical y)
// with 64KB smem so 2 blocks co-reside per SM.
// ---------------------------------------------------------------------------
__global__ void __launch_bounds__(256, 2) k_gemm(const float* __restrict__ x,
                                                 const float* __restrict__ W) {
    extern __shared__ float sm[];
    float* Xs = sm;                    // [64][128]  Xs[c*128+m]
    float* Ws = sm + 64 * 128;         // [64][128]  Ws[c*128+n]

    const int tid   = threadIdx.x;
    const int mbase = blockIdx.x * 128;
    const int nbase = blockIdx.y * 128;

    const int w    = tid >> 5;
    const int lane = tid & 31;
    const int m0 = (w & 1) * 64 + (lane & 7) * 8;
    const int n0 = (w >> 1) * 32 + (lane >> 3) * 8;
    const int grp = ((w & 1) << 3) | (lane & 7);    // 16 m-groups

    unsigned long long acc2[8][4];
#pragma unroll
    for (int i = 0; i < 8; ++i)
#pragma unroll
        for (int jp = 0; jp < 4; ++jp) acc2[i][jp] = 0ULL;

#pragma unroll 1
    for (int ph = 0; ph < 2; ++ph) {
        __syncthreads();               // previous-phase reads complete
        for (int e = tid; e < 2048; e += 256) {
            int c4 = e >> 7, m = e & 127;          // c4 0..15
            float4 v = *(const float4*)(x + (size_t)(mbase + m) * CIN + ph * 64 + c4 * 4);
            Xs[(c4 * 4 + 0) * 128 + m] = v.x;
            Xs[(c4 * 4 + 1) * 128 + m] = v.y;
            Xs[(c4 * 4 + 2) * 128 + m] = v.z;
            Xs[(c4 * 4 + 3) * 128 + m] = v.w;
        }
        for (int e = tid; e < 2048; e += 256) {
            int c4 = e >> 7, n = e & 127;
            float4 v = *(const float4*)(W + (size_t)(nbase + n) * CIN + ph * 64 + c4 * 4);
            Ws[(c4 * 4 + 0) * 128 + n] = v.x;
            Ws[(c4 * 4 + 1) * 128 + n] = v.y;
            Ws[(c4 * 4 + 2) * 128 + n] = v.z;
            Ws[(c4 * 4 + 3) * 128 + n] = v.w;
        }
        __syncthreads();

#pragma unroll 4
        for (int c = 0; c < 64; ++c) {
            float a8[8];
            *(float4*)(a8)     = *(const float4*)(Xs + c * 128 + m0);
            *(float4*)(a8 + 4) = *(const float4*)(Xs + c * 128 + m0 + 4);
            ulonglong2 b01 = *(const ulonglong2*)(Ws + c * 128 + n0);
            ulonglong2 b23 = *(const ulonglong2*)(Ws + c * 128 + n0 + 4);
            unsigned long long bb0 = b01.x, bb1 = b01.y, bb2 = b23.x, bb3 = b23.y;
#pragma unroll
            for (int i = 0; i < 8; ++i) {
                unsigned long long aa;
                DUP2(aa, __float_as_uint(a8[i]));
                FMA2(acc2[i][0], aa, bb0, acc2[i][0]);
                FMA2(acc2[i][1], aa, bb1, acc2[i][1]);
                FMA2(acc2[i][2], aa, bb2, acc2[i][2]);
                FMA2(acc2[i][3], aa, bb3, acc2[i][3]);
            }
        }
    }

    float acc[8][8];
#pragma unroll
    for (int i = 0; i < 8; ++i)
#pragma unroll
        for (int jp = 0; jp < 4; ++jp)
            UNPK2(acc[i][2 * jp], acc[i][2 * jp + 1], acc2[i][jp]);

#pragma unroll
    for (int i = 0; i < 8; ++i) {
        float* dst = g_y + (size_t)(mbase + m0 + i) * COUT + nbase + n0;
        *(float4*)(dst)     = make_float4(acc[i][0], acc[i][1], acc[i][2], acc[i][3]);
        *(float4*)(dst + 4) = make_float4(acc[i][4], acc[i][5], acc[i][6], acc[i][7]);
    }

    // ---- fused weighted BN stats ------------------------------------------
    float cw[8];
#pragma unroll
    for (int i = 0; i < 8; ++i) cw[i] = (float)g_cnt[mbase + m0 + i];

    float s[8], sq[8];
#pragma unroll
    for (int j = 0; j < 8; ++j) { s[j] = 0.0f; sq[j] = 0.0f; }
#pragma unroll
    for (int i = 0; i < 8; ++i)
#pragma unroll
        for (int j = 0; j < 8; ++j) {
            float vv = acc[i][j];
            s[j]  = fmaf(cw[i], vv, s[j]);
            sq[j] = fmaf(cw[i] * vv, vv, sq[j]);
        }

    __syncthreads();                   // smem free for reduction buffers
    float* red  = sm;                  // [(n)*17 + grp], 128*17 floats
    float* red2 = sm + 128 * 17;       // fits in 64KB region
#pragma unroll
    for (int j = 0; j < 8; ++j) {
        red [(n0 + j) * 17 + grp] = s[j];
        red2[(n0 + j) * 17 + grp] = sq[j];
    }
    __syncthreads();

    {
        int col  = tid & 127;
        const float* src = (tid < 128) ? red : red2;
        float acc1 = 0.0f;
#pragma unroll
        for (int g = 0; g < 16; ++g) acc1 += src[col * 17 + g];
        float* dst = (tid < 128) ? g_psum : g_psumsq;
        dst[blockIdx.x * COUT + nbase + col] = acc1;
    }
}

// ---------------------------------------------------------------------------
__global__ void k_finalize(const float* __restrict__ gamma,
                           const float* __restrict__ beta) {
    const int o = threadIdx.x;   // 1 block, 256 threads
    float s0 = 0, s1 = 0, s2 = 0, s3 = 0;
    float q0 = 0, q1 = 0, q2 = 0, q3 = 0;
#pragma unroll 8
    for (int r = 0; r < 64; ++r) {
        s0 += g_psum[(4 * r + 0) * COUT + o];
        s1 += g_psum[(4 * r + 1) * COUT + o];
        s2 += g_psum[(4 * r + 2) * COUT + o];
        s3 += g_psum[(4 * r + 3) * COUT + o];
        q0 += g_psumsq[(4 * r + 0) * COUT + o];
        q1 += g_psumsq[(4 * r + 1) * COUT + o];
        q2 += g_psumsq[(4 * r + 2) * COUT + o];
        q3 += g_psumsq[(4 * r + 3) * COUT + o];
    }
    float s  = (s0 + s1) + (s2 + s3);
    float sq = (q0 + q1) + (q2 + q3);
    const float invn = 1.0f / (float)((size_t)NQ * KNN);
    float mean = s * invn;
    float var  = sq * invn - mean * mean;
    float inv  = rsqrtf(var + BN_EPS);
    float sc   = gamma[o] * inv;
    g_scale[o] = sc;
    g_shift[o] = beta[o] - mean * sc;
}

// ---------------------------------------------------------------------------
// Fused gather + max/min over K + BN affine + ReLU; re-zeroes g_cnt for the
// next replay (module-load zero-init covers the first call).
// ---------------------------------------------------------------------------
__global__ void __launch_bounds__(256) k_pool(float* __restrict__ out) {
    __shared__ int sidx[64];
    const int tid = threadIdx.x;
    if (tid < 64) sidx[tid] = g_idx[(size_t)blockIdx.x * 64 + tid];
    __syncthreads();

    const int qi = tid >> 6;               // 0..3
    const int c4 = tid & 63;               // float4 lane over 256 ch
    const int q  = blockIdx.x * 4 + qi;
    const int b  = q >> 11;
    const float4* yb = (const float4*)g_y + (size_t)b * NPTS * 64;

    float4 mx = make_float4(-3.4e38f, -3.4e38f, -3.4e38f, -3.4e38f);
    float4 mn = make_float4( 3.4e38f,  3.4e38f,  3.4e38f,  3.4e38f);
#pragma unroll
    for (int k = 0; k < KNN; ++k) {
        float4 v = yb[(size_t)sidx[qi * 16 + k] * 64 + c4];
        mx.x = fmaxf(mx.x, v.x); mn.x = fminf(mn.x, v.x);
        mx.y = fmaxf(mx.y, v.y); mn.y = fminf(mn.y, v.y);
        mx.z = fmaxf(mx.z, v.z); mn.z = fminf(mn.z, v.z);
        mx.w = fmaxf(mx.w, v.w); mn.w = fminf(mn.w, v.w);
    }
    float4 sc = ((const float4*)g_scale)[c4];
    float4 sh = ((const float4*)g_shift)[c4];
    float4 r;
    r.x = fmaxf(fmaf(sc.x >= 0.f ? mx.x : mn.x, sc.x, sh.x), 0.f);
    r.y = fmaxf(fmaf(sc.y >= 0.f ? mx.y : mn.y, sc.y, sh.y), 0.f);
    r.z = fmaxf(fmaf(sc.z >= 0.f ? mx.z : mn.z, sc.z, sh.z), 0.f);
    r.w = fmaxf(fmaf(sc.w >= 0.f ? mx.w : mn.w, sc.w, sh.w), 0.f);
    ((float4*)out)[(size_t)q * 64 + c4] = r;

    if (tid < 8) g_cnt[blockIdx.x * 8 + tid] = 0;   // 4096 blocks x 8 = 32768
}

// ---------------------------------------------------------------------------
extern "C" void kernel_launch(void* const* d_in, const int* in_sizes, int n_in,
                              void* d_out, int out_size) {
    const float* x     = (const float*)d_in[0];
    const float* xyz   = (const float*)d_in[1];
    const float* W     = (const float*)d_in[2];
    // d_in[3] = bias: cancels analytically
    const float* gamma = (const float*)d_in[4];
    const float* beta  = (const float*)d_in[5];
    float* out = (float*)d_out;

    const int np_elems  = NQ * COUT;
    const int xyz_elems = NQ * 3;
    const int write_xyz = (out_size >= np_elems + xyz_elems) ? 1 : 0;
    float* out_xyz = out + np_elems;

    const int knn_smem  = NPTS * (int)sizeof(float4) + 64 * NSEG * KNN * 8; // 96 KB
    const int gemm_smem = 2 * 64 * 128 * (int)sizeof(float);                // 64 KB
    cudaFuncSetAttribute(k_knn,  cudaFuncAttributeMaxDynamicSharedMemorySize, knn_smem);
    cudaFuncSetAttribute(k_gemm, cudaFuncAttributeMaxDynamicSharedMemorySize, gemm_smem);

    k_knn<<<BATCH * (SQ / 64), 256, knn_smem>>>(xyz, out_xyz, write_xyz);
    dim3 gg(NROWS / 128, COUT / 128);
    k_gemm<<<gg, 256, gemm_smem>>>(x, W);
    k_finalize<<<1, COUT>>>(gamma, beta);
    k_pool<<<NQ / 4, 256>>>(out);
}